// round 1
// baseline (speedup 1.0000x reference)
#include <cuda_runtime.h>

#define Bsz 64
#define Tt  512
#define Ii  512
#define Hh  512

// hidden state, double buffered, k-major: [dir][parity][k*64 + b]
__device__ float g_h[2][2][Hh * Bsz];
// per-step arrival counters per direction
__device__ int g_cnt[2][Tt];

// ---------------------------------------------------------------------------
// init: zero counters, stage h0 (transposed to k-major)
// ---------------------------------------------------------------------------
__global__ void init_kernel(const float* __restrict__ h0f,
                            const float* __restrict__ h0b) {
    int idx = blockIdx.x * blockDim.x + threadIdx.x;   // 0..32767
    int b = idx >> 9;
    int k = idx & 511;
    g_h[0][0][k * Bsz + b] = h0f[idx];
    g_h[1][0][k * Bsz + b] = h0b[idx];
    if (idx < 2 * Tt) ((int*)g_cnt)[idx] = 0;
}

// ---------------------------------------------------------------------------
// Phase 1: y[b*T+t][j] = x[b,t,:] . W[j,:] + bias[j]   (j in [0,2H))
// rows m = b*T+t (32768), cols n (1024: first 512 fwd, next 512 bwd)
// 128x64 tile, BK=32, 256 threads, 8x4 microtile
// ---------------------------------------------------------------------------
#define BM 128
#define BN 64
#define BK 32
#define ASP 132
#define BSP 68

__global__ __launch_bounds__(256) void xproj_kernel(
    const float* __restrict__ x,
    const float* __restrict__ Wxf, const float* __restrict__ bxf,
    const float* __restrict__ Wxb, const float* __restrict__ bxb,
    float* __restrict__ y)
{
    __shared__ float As[BK][ASP];
    __shared__ float Bs[BK][BSP];
    int tid = threadIdx.x;
    int m0 = blockIdx.y * BM;
    int n0 = blockIdx.x * BN;

    const float* W;
    const float* bias;
    int jl;
    if (n0 < Hh) { W = Wxf; bias = bxf; jl = n0; }
    else         { W = Wxb; bias = bxb; jl = n0 - Hh; }

    int tx = tid & 15;   // n: 4 cols each
    int ty = tid >> 4;   // m: 8 rows each

    float acc[8][4];
#pragma unroll
    for (int i = 0; i < 8; i++)
#pragma unroll
        for (int j = 0; j < 4; j++) acc[i][j] = 0.f;

    for (int kc = 0; kc < Ii; kc += BK) {
        // A tile: 128 rows x 32 k = 1024 float4
#pragma unroll
        for (int r = 0; r < 4; ++r) {
            int idx = tid + 256 * r;
            int row = idx >> 3, c4 = idx & 7;
            float4 v = *(const float4*)&x[(m0 + row) * Ii + kc + c4 * 4];
            As[c4 * 4 + 0][row] = v.x;
            As[c4 * 4 + 1][row] = v.y;
            As[c4 * 4 + 2][row] = v.z;
            As[c4 * 4 + 3][row] = v.w;
        }
        // B tile: 64 rows x 32 k = 512 float4
#pragma unroll
        for (int r = 0; r < 2; ++r) {
            int idx = tid + 256 * r;
            int row = idx >> 3, c4 = idx & 7;
            float4 v = *(const float4*)&W[(jl + row) * Ii + kc + c4 * 4];
            Bs[c4 * 4 + 0][row] = v.x;
            Bs[c4 * 4 + 1][row] = v.y;
            Bs[c4 * 4 + 2][row] = v.z;
            Bs[c4 * 4 + 3][row] = v.w;
        }
        __syncthreads();
#pragma unroll
        for (int kk = 0; kk < BK; ++kk) {
            float4 b4 = *(const float4*)&Bs[kk][tx * 4];
            float4 a0 = *(const float4*)&As[kk][ty * 8];
            float4 a1 = *(const float4*)&As[kk][ty * 8 + 4];
            float av[8] = {a0.x, a0.y, a0.z, a0.w, a1.x, a1.y, a1.z, a1.w};
            float bv[4] = {b4.x, b4.y, b4.z, b4.w};
#pragma unroll
            for (int i = 0; i < 8; i++)
#pragma unroll
                for (int j = 0; j < 4; j++)
                    acc[i][j] = fmaf(av[i], bv[j], acc[i][j]);
        }
        __syncthreads();
    }

    float4 bias4 = *(const float4*)&bias[jl + tx * 4];
#pragma unroll
    for (int i = 0; i < 8; i++) {
        int m = m0 + ty * 8 + i;
        float4 o;
        o.x = acc[i][0] + bias4.x;
        o.y = acc[i][1] + bias4.y;
        o.z = acc[i][2] + bias4.z;
        o.w = acc[i][3] + bias4.w;
        *(float4*)&y[(size_t)m * (2 * Hh) + n0 + tx * 4] = o;
    }
}

// ---------------------------------------------------------------------------
// Phase 2: persistent recurrence kernel.
// 128 CTAs: blocks 0..63 forward, 64..127 backward. Each owns 8 hidden cols.
// Per step: h_new[b][j] = tanh(xp[t][b][j] + sum_k h[b][k]*Wh[j][k])
// 4b x 4j register tiles, 8-way K split across warps, SMEM reduction.
// ---------------------------------------------------------------------------
__global__ __launch_bounds__(256) void rnn_kernel(
    const float* __restrict__ Whf, const float* __restrict__ Whb,
    float* __restrict__ y, float* __restrict__ out_hT)
{
    extern __shared__ float smem[];
    float* sh_wt = smem;                       // [512][8]   transposed Wh slice
    float* sh_ht = smem + 4096;                // 2 x [64][68] h chunk (k-major)
    float* red   = smem + 4096 + 2 * 64 * 68;  // [512][9]   partials

    int tid  = threadIdx.x;
    int bx   = blockIdx.x;
    int dir  = bx >> 6;
    int jblk = (bx & 63) * 8;
    const float* Wh = dir ? Whb : Whf;

    // stage Wh slice, transposed to [k][j]
    for (int r = 0; r < 16; ++r) {
        int idx = tid + 256 * r;
        int j = idx >> 9, k = idx & 511;
        sh_wt[k * 8 + j] = Wh[(jblk + j) * Hh + k];
    }
    __syncthreads();

    int sl = tid >> 5;        // warp = k-slice (8 k per 64-chunk)
    int sp = tid & 31;
    int b0 = (sp & 15) * 4;
    int j0 = (sp >> 4) * 4;
    int yhalf = dir * Hh;

    // my 2 outputs in j-major order o = j*64 + b
    int o1 = tid, o2 = tid + 256;
    int j1 = o1 >> 6, b1 = o1 & 63;
    int j2 = o2 >> 6, b2 = o2 & 63;

    for (int s = 0; s < Tt; ++s) {
        int t = dir ? (Tt - 1 - s) : s;
        const float* hsrc = g_h[dir][s & 1];
        float* hdst       = g_h[dir][(s + 1) & 1];

        size_t ybase = (size_t)t * (2 * Hh) + yhalf + jblk;
        float xp1 = y[(size_t)b1 * (Tt * 2 * Hh) + ybase + j1];
        float xp2 = y[(size_t)b2 * (Tt * 2 * Hh) + ybase + j2];

        float acc[4][4];
#pragma unroll
        for (int i = 0; i < 4; i++)
#pragma unroll
            for (int j = 0; j < 4; j++) acc[i][j] = 0.f;

        // prefetch chunk 0 (L2, bypass L1: state written by other SMs)
        float4 pf[4];
#pragma unroll
        for (int r = 0; r < 4; ++r) {
            int idx = tid + 256 * r;
            int kk = idx >> 4, b4 = idx & 15;
            pf[r] = __ldcg((const float4*)&hsrc[kk * Bsz + b4 * 4]);
        }
        int cur = 0;
        for (int c = 0; c < 8; ++c) {
            float* buf = sh_ht + cur * (64 * 68);
#pragma unroll
            for (int r = 0; r < 4; ++r) {
                int idx = tid + 256 * r;
                int kk = idx >> 4, b4 = idx & 15;
                *(float4*)&buf[kk * 68 + b4 * 4] = pf[r];
            }
            __syncthreads();
            if (c < 7) {
#pragma unroll
                for (int r = 0; r < 4; ++r) {
                    int idx = tid + 256 * r;
                    int kk = idx >> 4, b4 = idx & 15;
                    pf[r] = __ldcg(
                        (const float4*)&hsrc[((c + 1) * 64 + kk) * Bsz + b4 * 4]);
                }
            }
            int kbase = c * 64;
#pragma unroll
            for (int u = 0; u < 8; ++u) {
                int kk = sl * 8 + u;
                float4 h4 = *(const float4*)&buf[kk * 68 + b0];
                float4 w4 = *(const float4*)&sh_wt[(kbase + kk) * 8 + j0];
                float hv[4] = {h4.x, h4.y, h4.z, h4.w};
                float wv[4] = {w4.x, w4.y, w4.z, w4.w};
#pragma unroll
                for (int ji = 0; ji < 4; ji++)
#pragma unroll
                    for (int bi = 0; bi < 4; bi++)
                        acc[ji][bi] = fmaf(wv[ji], hv[bi], acc[ji][bi]);
            }
            cur ^= 1;
        }
        __syncthreads();
        // write partials
#pragma unroll
        for (int ji = 0; ji < 4; ji++)
#pragma unroll
            for (int bi = 0; bi < 4; bi++)
                red[((j0 + ji) * 64 + (b0 + bi)) * 9 + sl] = acc[ji][bi];
        __syncthreads();
        // gather + activation
        float v1 = xp1, v2 = xp2;
#pragma unroll
        for (int q = 0; q < 8; ++q) {
            v1 += red[o1 * 9 + q];
            v2 += red[o2 * 9 + q];
        }
        v1 = tanhf(v1);
        v2 = tanhf(v2);

        y[(size_t)b1 * (Tt * 2 * Hh) + ybase + j1] = v1;
        y[(size_t)b2 * (Tt * 2 * Hh) + ybase + j2] = v2;
        hdst[(jblk + j1) * Bsz + b1] = v1;
        hdst[(jblk + j2) * Bsz + b2] = v2;
        if (s == Tt - 1) {
            float* ht = out_hT + (size_t)dir * (Bsz * Hh);
            ht[b1 * Hh + jblk + j1] = v1;
            ht[b2 * Hh + jblk + j2] = v2;
        }

        if (s < Tt - 1) {
            __threadfence();
            __syncthreads();
            if (tid == 0) {
                atomicAdd(&g_cnt[dir][s], 1);
                while (((volatile int*)&g_cnt[dir][s])[0] < 64) {}
            }
            __syncthreads();
            __threadfence();
        }
    }
}

// ---------------------------------------------------------------------------
extern "C" void kernel_launch(void* const* d_in, const int* in_sizes, int n_in,
                              void* d_out, int out_size) {
    const float* x    = (const float*)d_in[0];
    const float* h0_f = (const float*)d_in[1];
    const float* h0_b = (const float*)d_in[2];
    const float* Wxf_w = (const float*)d_in[3];
    const float* Wxf_b = (const float*)d_in[4];
    const float* Whf_w = (const float*)d_in[5];
    const float* Wxb_w = (const float*)d_in[6];
    const float* Wxb_b = (const float*)d_in[7];
    const float* Whb_w = (const float*)d_in[8];

    float* y  = (float*)d_out;
    float* hT = y + (size_t)Bsz * Tt * 2 * Hh;

    static bool attr_done = false;
    // idempotent, host-side only; not a stream op (safe under capture)
    cudaFuncSetAttribute(rnn_kernel,
                         cudaFuncAttributeMaxDynamicSharedMemorySize,
                         72 * 1024);

    init_kernel<<<64, 512>>>(h0_f, h0_b);

    dim3 grid(2 * Hh / BN, (Bsz * Tt) / BM);
    xproj_kernel<<<grid, 256>>>(x, Wxf_w, Wxf_b, Wxb_w, Wxb_b, y);

    rnn_kernel<<<128, 256, 72 * 1024>>>(Whf_w, Whb_w, y, hT);
    (void)attr_done; (void)in_sizes; (void)n_in; (void)out_size;
}